// round 5
// baseline (speedup 1.0000x reference)
#include <cuda_runtime.h>
#include <cuda_bf16.h>
#include <cstdint>

// ---------------- problem constants ----------------
#define B     16
#define CIN   256
#define COUT  256
#define HW    4096
#define STY   512
#define KTOT  2304          // 9 taps * 256 ci; k = tap*256 + ci
#define NSTG  72            // K stages of 32

// ---------------- scratch ----------------
__device__ float g_s[B * CIN];
__device__ __align__(16) __nv_bfloat16 g_wbh[(size_t)B * COUT * KTOT]; // [b][co][k]
__device__ __align__(16) __nv_bfloat16 g_wbl[(size_t)B * COUT * KTOT];
__device__ __align__(16) __nv_bfloat16 g_xh[(size_t)B * HW * CIN];     // [b][pix][ci]
__device__ __align__(16) __nv_bfloat16 g_xl[(size_t)B * HW * CIN];
__device__ __align__(64) unsigned char g_zero64[64];                    // zero-init

// ---------------- helpers ----------------
__device__ __forceinline__ uint32_t smem_u32(const void* p) {
    uint32_t a;
    asm("{ .reg .u64 t; cvta.to.shared.u64 t, %1; cvt.u32.u64 %0, t; }" : "=r"(a) : "l"(p));
    return a;
}
__device__ __forceinline__ void ldsm_x4(uint32_t* r, uint32_t addr) {
    asm volatile("ldmatrix.sync.aligned.m8n8.x4.shared.b16 {%0,%1,%2,%3}, [%4];"
                 : "=r"(r[0]), "=r"(r[1]), "=r"(r[2]), "=r"(r[3]) : "r"(addr));
}
__device__ __forceinline__ void mma16816(float* c, const uint32_t* a,
                                         uint32_t b0, uint32_t b1) {
    asm volatile("mma.sync.aligned.m16n8k16.row.col.f32.bf16.bf16.f32 "
                 "{%0,%1,%2,%3}, {%4,%5,%6,%7}, {%8,%9}, {%0,%1,%2,%3};"
                 : "+f"(c[0]), "+f"(c[1]), "+f"(c[2]), "+f"(c[3])
                 : "r"(a[0]), "r"(a[1]), "r"(a[2]), "r"(a[3]), "r"(b0), "r"(b1));
}
__device__ __forceinline__ void cpa16(uint32_t dst, const void* src) {
    asm volatile("cp.async.ca.shared.global [%0], [%1], 16;" :: "r"(dst), "l"(src));
}
#define CPA_COMMIT() asm volatile("cp.async.commit_group;" ::: "memory")
#define CPA_WAIT1()  asm volatile("cp.async.wait_group 1;" ::: "memory")
#define CPA_WAIT0()  asm volatile("cp.async.wait_group 0;" ::: "memory")

// ---------------- smem layout: 80B-padded rows ----------------
// per buffer: AH 128 rows, AL 128, BH 256, BL 256 (each 80B) = 61440B
#define ROWB    80
#define A_HI_O  0
#define A_LO_O  10240
#define B_HI_O  20480
#define B_LO_O  40960
#define BUFB    61440
#define SMEM_TOTAL (2 * BUFB)   // 122880

// ---------------------------------------------------------------------------
__global__ void style_kernel(const float* __restrict__ w_style,
                             const float* __restrict__ aff_w,
                             const float* __restrict__ aff_b) {
    int warp = blockIdx.x * (blockDim.x >> 5) + (threadIdx.x >> 5);
    int lane = threadIdx.x & 31;
    if (warp >= B * CIN) return;
    int b  = warp / CIN;
    int ci = warp % CIN;
    const float4* ws = reinterpret_cast<const float4*>(w_style + (size_t)b * STY);
    const float4* aw = reinterpret_cast<const float4*>(aff_w  + (size_t)ci * STY);
    float sum = 0.f;
    #pragma unroll
    for (int j = lane; j < STY / 4; j += 32) {
        float4 a = ws[j], c = aw[j];
        sum += a.x * c.x + a.y * c.y + a.z * c.z + a.w * c.w;
    }
    #pragma unroll
    for (int o = 16; o; o >>= 1) sum += __shfl_xor_sync(0xffffffffu, sum, o);
    if (lane == 0) g_s[b * CIN + ci] = sum + aff_b[ci] + 1.0f;
}

// ---------------------------------------------------------------------------
// modulate + demodulate -> split-bf16 weights [b][co][k], k = tap*256+ci
// ---------------------------------------------------------------------------
__global__ void modulate_kernel(const float* __restrict__ Wf) {
    int co = blockIdx.x;
    int b  = blockIdx.y;
    int ci = threadIdx.x;

    float s = g_s[b * CIN + ci];
    const float* wp = Wf + ((size_t)co * CIN + ci) * 9;
    float m[9];
    float ss = 0.f;
    #pragma unroll
    for (int t = 0; t < 9; t++) { m[t] = wp[t] * s; ss += m[t] * m[t]; }

    __shared__ float red[256];
    red[ci] = ss;
    __syncthreads();
    #pragma unroll
    for (int st = 128; st > 0; st >>= 1) {
        if (ci < st) red[ci] += red[ci + st];
        __syncthreads();
    }
    float d = rsqrtf(red[0] + 1e-8f);

    size_t base = ((size_t)b * COUT + co) * KTOT;
    #pragma unroll
    for (int t = 0; t < 9; t++) {
        float w = m[t] * d;
        __nv_bfloat16 hi = __float2bfloat16_rn(w);
        __nv_bfloat16 lo = __float2bfloat16_rn(w - __bfloat162float(hi));
        g_wbh[base + t * 256 + ci] = hi;
        g_wbl[base + t * 256 + ci] = lo;
    }
}

// ---------------------------------------------------------------------------
// split/transpose x [b][ci][pix] fp32 -> [b][pix][ci] bf16 hi/lo
// ---------------------------------------------------------------------------
__global__ void split_kernel(const float* __restrict__ x) {
    __shared__ float t[32][33];
    int b  = blockIdx.z;
    int cb = blockIdx.y * 32;
    int pb = blockIdx.x * 32;
    int tx = threadIdx.x, ty = threadIdx.y;

    const float* xp = x + ((size_t)b * CIN + cb) * HW + pb;
    #pragma unroll
    for (int i = ty; i < 32; i += 8)
        t[i][tx] = xp[(size_t)i * HW + tx];
    __syncthreads();
    #pragma unroll
    for (int i = ty; i < 32; i += 8) {
        float v = t[tx][i];                      // ci = cb+tx, pix = pb+i
        __nv_bfloat16 h = __float2bfloat16_rn(v);
        size_t o = ((size_t)b * HW + pb + i) * CIN + cb + tx;
        g_xh[o] = h;
        g_xl[o] = __float2bfloat16_rn(v - __bfloat162float(h));
    }
}

// ---------------------------------------------------------------------------
// conv as implicit GEMM. CTA: M=128 px, N=256 co, 256 thr = 8 warps (2M x 4N),
// warp tile 64x64, K staged 32, cp.async double buffer.
// ---------------------------------------------------------------------------
__global__ void __launch_bounds__(256, 1)
conv_kernel(float* __restrict__ out) {
    extern __shared__ __align__(16) char smem[];
    const uint32_t sbase = smem_u32(smem);

    const int tid   = threadIdx.x;
    const int wid   = tid >> 5;
    const int lane  = tid & 31;
    const int strip = blockIdx.x;          // 0..31
    const int b     = blockIdx.y;

    const int wm = (wid & 1) * 64;         // warp M origin (0/64)
    const int wn = (wid >> 1) * 64;        // warp N origin (0..192)

    // ldmatrix lane addressing (validated in R4)
    const int lr = lane & 15;
    const int kb = ((lane >> 4) & 1) * 16;

    // A staging: thread -> one A row (hi for tid<128, lo for tid>=128)
    const int arow  = tid & 127;
    const int aprec = tid >> 7;
    const int apy   = (strip * 128 + arow) >> 6;   // image row
    const int apx   = (strip * 128 + arow) & 63;   // image col

    const __nv_bfloat16* xsrc = (aprec ? g_xl : g_xh) + (size_t)b * HW * CIN;
    const __nv_bfloat16* wh = g_wbh + (size_t)b * COUT * KTOT;
    const __nv_bfloat16* wl = g_wbl + (size_t)b * COUT * KTOT;

    float acc[4][8][4];
    #pragma unroll
    for (int i = 0; i < 4; i++)
        #pragma unroll
        for (int j = 0; j < 8; j++)
            #pragma unroll
            for (int q = 0; q < 4; q++) acc[i][j][q] = 0.f;

    // ---- issue cp.async for stage s into buffer buf ----
    auto stage_issue = [&](int s, int buf) {
        const uint32_t bb = sbase + buf * BUFB;
        // A row
        {
            int tap = s >> 3, ci0 = (s & 7) << 5;
            int y = apy + tap / 3 - 1;
            int xx = apx + tap % 3 - 1;
            const void* src;
            if ((unsigned)y < 64u && (unsigned)xx < 64u)
                src = xsrc + ((size_t)(y * 64 + xx) * CIN + ci0);
            else
                src = g_zero64;
            uint32_t dst = bb + (aprec ? A_LO_O : A_HI_O) + arow * ROWB;
            const char* sp = (const char*)src;
            cpa16(dst,      sp);
            cpa16(dst + 16, (unsigned)y < 64u && (unsigned)xx < 64u ? sp + 16 : sp);
            cpa16(dst + 32, (unsigned)y < 64u && (unsigned)xx < 64u ? sp + 32 : sp);
            cpa16(dst + 48, (unsigned)y < 64u && (unsigned)xx < 64u ? sp + 48 : sp);
        }
        // B rows: hi co=tid, lo co=tid
        {
            const __nv_bfloat16* sh = wh + (size_t)tid * KTOT + s * 32;
            const __nv_bfloat16* sl = wl + (size_t)tid * KTOT + s * 32;
            uint32_t dh = bb + B_HI_O + tid * ROWB;
            uint32_t dl = bb + B_LO_O + tid * ROWB;
            cpa16(dh,      sh);
            cpa16(dh + 16, sh + 8);
            cpa16(dh + 32, sh + 16);
            cpa16(dh + 48, sh + 24);
            cpa16(dl,      sl);
            cpa16(dl + 16, sl + 8);
            cpa16(dl + 32, sl + 16);
            cpa16(dl + 48, sl + 24);
        }
        CPA_COMMIT();
    };

    stage_issue(0, 0);

    for (int s = 0; s < NSTG; s++) {
        const int buf = s & 1;
        if (s + 1 < NSTG) { stage_issue(s + 1, buf ^ 1); CPA_WAIT1(); }
        else              { CPA_WAIT0(); }
        __syncthreads();

        const uint32_t bb = sbase + buf * BUFB;
        #pragma unroll
        for (int k16 = 0; k16 < 2; k16++) {
            const int kc = kb + k16 * 32;
            uint32_t ah[16], al[16], bh[16], bl[16];
            #pragma unroll
            for (int mt = 0; mt < 4; mt++)
                ldsm_x4(ah + mt * 4, bb + A_HI_O + (wm + mt * 16 + lr) * ROWB + kc);
            #pragma unroll
            for (int g = 0; g < 4; g++)
                ldsm_x4(bh + g * 4, bb + B_HI_O + (wn + g * 16 + lr) * ROWB + kc);
            // term hh
            #pragma unroll
            for (int mt = 0; mt < 4; mt++)
                #pragma unroll
                for (int g = 0; g < 4; g++)
                    #pragma unroll
                    for (int j = 0; j < 2; j++)
                        mma16816(acc[mt][g * 2 + j], ah + mt * 4,
                                 bh[g * 4 + j], bh[g * 4 + j + 2]);
            // term hl
            #pragma unroll
            for (int g = 0; g < 4; g++)
                ldsm_x4(bl + g * 4, bb + B_LO_O + (wn + g * 16 + lr) * ROWB + kc);
            #pragma unroll
            for (int mt = 0; mt < 4; mt++)
                #pragma unroll
                for (int g = 0; g < 4; g++)
                    #pragma unroll
                    for (int j = 0; j < 2; j++)
                        mma16816(acc[mt][g * 2 + j], ah + mt * 4,
                                 bl[g * 4 + j], bl[g * 4 + j + 2]);
            // term lh
            #pragma unroll
            for (int mt = 0; mt < 4; mt++)
                ldsm_x4(al + mt * 4, bb + A_LO_O + (wm + mt * 16 + lr) * ROWB + kc);
            #pragma unroll
            for (int mt = 0; mt < 4; mt++)
                #pragma unroll
                for (int g = 0; g < 4; g++)
                    #pragma unroll
                    for (int j = 0; j < 2; j++)
                        mma16816(acc[mt][g * 2 + j], al + mt * 4,
                                 bh[g * 4 + j], bh[g * 4 + j + 2]);
        }
        __syncthreads();
    }

    // ---- epilogue: out[b][co][pix] ----
    float* ob = out + (size_t)b * COUT * HW;
    #pragma unroll
    for (int mt = 0; mt < 4; mt++) {
        int m = strip * 128 + wm + mt * 16 + (lane >> 2);
        #pragma unroll
        for (int nt = 0; nt < 8; nt++) {
            int co = wn + nt * 8 + (lane & 3) * 2;
            const float* a = acc[mt][nt];
            float* p = ob + (size_t)co * HW + m;
            p[0]      = a[0];
            p[HW]     = a[1];
            p[8]      = a[2];
            p[HW + 8] = a[3];
        }
    }
}

// ---------------------------------------------------------------------------
extern "C" void kernel_launch(void* const* d_in, const int* in_sizes, int n_in,
                              void* d_out, int out_size) {
    const float* x       = (const float*)d_in[0];
    const float* w_style = (const float*)d_in[1];
    const float* Wf      = (const float*)d_in[2];
    const float* aff_w   = (const float*)d_in[3];
    const float* aff_b   = (const float*)d_in[4];
    float* out = (float*)d_out;

    style_kernel<<<(B * CIN + 7) / 8, 256>>>(w_style, aff_w, aff_b);
    modulate_kernel<<<dim3(COUT, B), 256>>>(Wf);
    split_kernel<<<dim3(HW / 32, CIN / 32, B), dim3(32, 8)>>>(x);

    cudaFuncSetAttribute(conv_kernel, cudaFuncAttributeMaxDynamicSharedMemorySize, SMEM_TOTAL);
    conv_kernel<<<dim3(32, B), 256, SMEM_TOTAL>>>(out);
}